// round 11
// baseline (speedup 1.0000x reference)
#include <cuda_runtime.h>
#include <cstdint>

#define TOK   16384
#define DIM   2048
#define NE    16
#define BT    128
#define NTHR  512

#define WPITCH_B 8208u                       // 2048 floats + 16 B pad per W row
#define WSMEM_B  (16u * 8208u)               // 131328
#define PBUF_OFF WSMEM_B                     // two [128][18] partial buffers
#define SMEM_BYTES (131328 + 2 * 128 * 18 * 4)   // 149760

__device__ __forceinline__ uint32_t smem_u32(const void* p) {
    uint32_t a;
    asm("{ .reg .u64 t; cvta.to.shared.u64 t, %1; cvt.u32.u64 %0, t; }" : "=r"(a) : "l"(p));
    return a;
}

#define CP_ASYNC16(saddr, gptr) \
    asm volatile("cp.async.cg.shared.global [%0], [%1], 16;" :: "r"(saddr), "l"(gptr))
#define CP_COMMIT() asm volatile("cp.async.commit_group;" ::: "memory")
#define CP_WAIT0()  asm volatile("cp.async.wait_group 0;" ::: "memory")

#define LDS64(a, b, addr) \
    asm volatile("ld.shared.v2.f32 {%0, %1}, [%2];" : "=f"(a), "=f"(b) : "r"(addr))
#define STS64(addr, a, b) \
    asm volatile("st.shared.v2.f32 [%0], {%1, %2};" :: "r"(addr), "f"(a), "f"(b))
#define LDS32(v, addr) asm volatile("ld.shared.f32 %0, [%1];" : "=f"(v) : "r"(addr))

// split v -> tf32 hi (RNA) + fp32 lo bits (HW truncates lo inside the MMA)
#define SPLIT(h, lo, v) do {                                   \
    asm("cvt.rna.tf32.f32 %0, %1;" : "=r"(h) : "f"(v));        \
    (lo) = __float_as_uint((v) - __uint_as_float(h));          \
} while (0)

#define MMA_TF32(d, a0, a1, a2, a3, b0, b1)                               \
    asm volatile("mma.sync.aligned.m16n8k8.row.col.f32.tf32.tf32.f32 "    \
        "{%0,%1,%2,%3}, {%4,%5,%6,%7}, {%8,%9}, {%0,%1,%2,%3};"           \
        : "+f"(d[0]), "+f"(d[1]), "+f"(d[2]), "+f"(d[3])                  \
        : "r"(a0), "r"(a1), "r"(a2), "r"(a3), "r"(b0), "r"(b1))

__global__ void __launch_bounds__(NTHR, 1)
gating_moe_kernel(const float* __restrict__ x,
                  const float* __restrict__ noise,
                  const float* __restrict__ W,
                  const float* __restrict__ b,
                  float* __restrict__ out)
{
    extern __shared__ float sm[];
    const uint32_t sb = smem_u32(sm);
    const int tid  = threadIdx.x;
    const int wid  = tid >> 5;
    const int l    = tid & 31;
    const int g    = l >> 2;            // fragment group (token row / expert col)
    const int pr   = l & 3;             // k-quad: phys dims [4pr, 4pr+4) per 16-dim group
    const int trow = (wid & 7) * 16;    // token rows [trow, trow+16)
    const int kh   = wid >> 3;          // k-half: dims [kh*1024, +1024)
    const int tok0 = blockIdx.x * BT;

    // ---- one-time W load into padded smem rows (pitch 8208 B, conflict-free) ----
    #pragma unroll
    for (int k = 0; k < 16; k++) {
        int gg = tid + NTHR * k;        // 16 B chunk id: e = gg/512, c4 = gg%512
        uint32_t dst = (uint32_t)(gg >> 9) * WPITCH_B + (uint32_t)(gg & 511) * 16u;
        CP_ASYNC16(sb + dst, (const char*)W + (size_t)gg * 16);
    }
    CP_COMMIT(); CP_WAIT0();
    __syncthreads();

    // ---- x straight from global: rows trow+g and trow+g+8, this warp's k-half ----
    const float* xr0 = x + (size_t)(tok0 + trow + g) * DIM + kh * 1024 + pr * 4;
    const float* xr1 = xr0 + 8 * DIM;

    // W smem row bases for expert tiles (e = g and e = 8+g)
    const uint32_t wr0 = sb + (uint32_t)g * WPITCH_B + (uint32_t)(kh * 1024 + pr * 4) * 4u;
    const uint32_t wr1 = wr0 + 8u * WPITCH_B;

    float d0[4] = {0.f, 0.f, 0.f, 0.f};   // experts 0-7
    float d1[4] = {0.f, 0.f, 0.f, 0.f};   // experts 8-15

    float4 bufA[2][4], bufB[2][4];
    #pragma unroll
    for (int u = 0; u < 4; u++) {
        bufA[0][u] = *(const float4*)(xr0 + u * 16);
        bufB[0][u] = *(const float4*)(xr1 + u * 16);
    }

    for (int j4 = 0; j4 < 16; j4++) {      // 16 iters x 4 groups x 16 dims = 1024 dims
        const int cur = j4 & 1;
        if (j4 < 15) {
            #pragma unroll
            for (int u = 0; u < 4; u++) {
                bufA[cur ^ 1][u] = *(const float4*)(xr0 + ((j4 + 1) * 4 + u) * 16);
                bufB[cur ^ 1][u] = *(const float4*)(xr1 + ((j4 + 1) * 4 + u) * 16);
            }
        }
        #pragma unroll
        for (int u = 0; u < 4; u++) {
            const float4 xa = bufA[cur][u];     // row trow+g,   4 dims
            const float4 xb = bufB[cur][u];     // row trow+g+8, 4 dims

            uint32_t ha[4], la[4], hb[4], lb[4];
            SPLIT(ha[0], la[0], xa.x); SPLIT(ha[1], la[1], xa.y);
            SPLIT(ha[2], la[2], xa.z); SPLIT(ha[3], la[3], xa.w);
            SPLIT(hb[0], lb[0], xb.x); SPLIT(hb[1], lb[1], xb.y);
            SPLIT(hb[2], lb[2], xb.z); SPLIT(hb[3], lb[3], xb.w);

            const uint32_t ko = (uint32_t)((j4 * 4 + u) * 64);
            float f0, f1, f2, f3, f4, f5, f6, f7;
            LDS64(f0, f1, wr0 + ko);        // tile0, step0: k = 4pr, 4pr+1
            LDS64(f2, f3, wr0 + ko + 8u);   // tile0, step1
            LDS64(f4, f5, wr1 + ko);        // tile1, step0
            LDS64(f6, f7, wr1 + ko + 8u);   // tile1, step1

            uint32_t wh[8], wl[8];
            SPLIT(wh[0], wl[0], f0); SPLIT(wh[1], wl[1], f1);
            SPLIT(wh[2], wl[2], f2); SPLIT(wh[3], wl[3], f3);
            SPLIT(wh[4], wl[4], f4); SPLIT(wh[5], wl[5], f5);
            SPLIT(wh[6], wl[6], f6); SPLIT(wh[7], wl[7], f7);

            // step0 (k pairs 4pr, 4pr+1)
            MMA_TF32(d0, ha[0], hb[0], ha[1], hb[1], wh[0], wh[1]);
            MMA_TF32(d0, ha[0], hb[0], ha[1], hb[1], wl[0], wl[1]);
            MMA_TF32(d0, la[0], lb[0], la[1], lb[1], wh[0], wh[1]);
            MMA_TF32(d1, ha[0], hb[0], ha[1], hb[1], wh[4], wh[5]);
            MMA_TF32(d1, ha[0], hb[0], ha[1], hb[1], wl[4], wl[5]);
            MMA_TF32(d1, la[0], lb[0], la[1], lb[1], wh[4], wh[5]);
            // step1 (k pairs 4pr+2, 4pr+3)
            MMA_TF32(d0, ha[2], hb[2], ha[3], hb[3], wh[2], wh[3]);
            MMA_TF32(d0, ha[2], hb[2], ha[3], hb[3], wl[2], wl[3]);
            MMA_TF32(d0, la[2], lb[2], la[3], lb[3], wh[2], wh[3]);
            MMA_TF32(d1, ha[2], hb[2], ha[3], hb[3], wh[6], wh[7]);
            MMA_TF32(d1, ha[2], hb[2], ha[3], hb[3], wl[6], wl[7]);
            MMA_TF32(d1, la[2], lb[2], la[3], lb[3], wh[6], wh[7]);
        }
    }

    // ---- k-half partials -> smem [128][18] per half ----
    {
        const uint32_t pb = sb + PBUF_OFF + (uint32_t)kh * 9216u;
        const int rA = trow + g;
        const int rB = rA + 8;
        STS64(pb + (uint32_t)(rA * 18 + 2 * pr) * 4u,     d0[0], d0[1]);
        STS64(pb + (uint32_t)(rB * 18 + 2 * pr) * 4u,     d0[2], d0[3]);
        STS64(pb + (uint32_t)(rA * 18 + 8 + 2 * pr) * 4u, d1[0], d1[1]);
        STS64(pb + (uint32_t)(rB * 18 + 8 + 2 * pr) * 4u, d1[2], d1[3]);
    }
    __syncthreads();

    // ---- epilogue: one token per thread (threads 0..127) ----
    if (tid < BT) {
        const int gtok = tok0 + tid;
        const float4* nz = (const float4*)(noise + (size_t)gtok * NE);
        float4 n0 = nz[0], n1 = nz[1], n2 = nz[2], n3 = nz[3];
        const float4* bb4 = (const float4*)b;
        float4 q0 = bb4[0], q1 = bb4[1], q2 = bb4[2], q3 = bb4[3];

        float nn[16] = {n0.x, n0.y, n0.z, n0.w, n1.x, n1.y, n1.z, n1.w,
                        n2.x, n2.y, n2.z, n2.w, n3.x, n3.y, n3.z, n3.w};
        float bv[16] = {q0.x, q0.y, q0.z, q0.w, q1.x, q1.y, q1.z, q1.w,
                        q2.x, q2.y, q2.z, q2.w, q3.x, q3.y, q3.z, q3.w};

        const uint32_t pb = sb + PBUF_OFF;
        float v[16];
        #pragma unroll
        for (int e = 0; e < 16; e++) {
            float l0, l1;
            LDS32(l0, pb + (uint32_t)(tid * 18 + e) * 4u);
            LDS32(l1, pb + 9216u + (uint32_t)(tid * 18 + e) * 4u);
            v[e] = (l0 + l1) + bv[e] + 0.1f * nn[e];
        }

        // top-2 (stable: earlier index wins ties, matching jax top_k)
        float v1 = -1e30f, v2 = -1e30f;
        int   i1 = -1,     i2 = -1;
        #pragma unroll
        for (int e = 0; e < 16; e++) {
            float val = v[e];
            if (val > v1)      { v2 = v1; i2 = i1; v1 = val; i1 = e; }
            else if (val > v2) { v2 = val; i2 = e; }
        }

        float ew  = expf(v2 - v1);
        float inv = 1.0f / (1.0f + ew);
        float w1  = inv;
        float w2  = ew * inv;

        float o[16];
        #pragma unroll
        for (int e = 0; e < 16; e++)
            o[e] = (e == i1) ? w1 : ((e == i2) ? w2 : 0.0f);

        float4* op = (float4*)(out + (size_t)gtok * NE);
        op[0] = make_float4(o[0],  o[1],  o[2],  o[3]);
        op[1] = make_float4(o[4],  o[5],  o[6],  o[7]);
        op[2] = make_float4(o[8],  o[9],  o[10], o[11]);
        op[3] = make_float4(o[12], o[13], o[14], o[15]);
    }
}

extern "C" void kernel_launch(void* const* d_in, const int* in_sizes, int n_in,
                              void* d_out, int out_size)
{
    const float* x     = (const float*)d_in[0];
    const float* noise = (const float*)d_in[1];
    const float* W     = (const float*)d_in[2];
    const float* b     = (const float*)d_in[3];
    float* out = (float*)d_out;

    cudaFuncSetAttribute(gating_moe_kernel,
                         cudaFuncAttributeMaxDynamicSharedMemorySize, SMEM_BYTES);
    gating_moe_kernel<<<TOK / BT, NTHR, SMEM_BYTES>>>(x, noise, W, b, out);
}